// round 15
// baseline (speedup 1.0000x reference)
#include <cuda_runtime.h>
#include <cuda_fp16.h>
#include <math.h>
#include <stdint.h>

// Problem constants
#define Bc   2
#define Sc   2048
#define Dc   2048
#define Hc   16
#define HDc  128
#define ROTc 64
#define Mc   (Bc*Sc)
#define NQKV (3*Dc)   // 6144

// ---------------------------------------------------------------------------
// Scratch
// ---------------------------------------------------------------------------
__device__ float  g_cnt[Bc*Sc];
__device__ float2 g_rope[(size_t)Bc*Sc*32];
__device__ half   g_hsh [(size_t)Mc*Dc];
__device__ half   g_wh  [(size_t)NQKV*Dc];   // packed [Wq;Wk;Wv]
__device__ half   g_woh [(size_t)Dc*Dc];
__device__ half   g_qkvh[(size_t)Mc*NQKV];
__device__ half   g_abh [(size_t)Mc*Dc];
__device__ half   g_qh  [(size_t)Mc*Dc];
__device__ half   g_kh  [(size_t)Mc*Dc];
__device__ half   g_vh  [(size_t)Mc*Dc];

// ---------------------------------------------------------------------------
// helpers
// ---------------------------------------------------------------------------
__device__ __forceinline__ uint32_t smem_u32(const void* p) {
    uint32_t a;
    asm("{ .reg .u64 t; cvta.to.shared.u64 t, %1; cvt.u32.u64 %0, t; }"
        : "=r"(a) : "l"(p));
    return a;
}
__device__ __forceinline__ uint32_t pack_h2(float lo, float hi) {
    half2 h = __floats2half2_rn(lo, hi);
    return *(uint32_t*)&h;
}
__device__ __forceinline__ void cp16(uint32_t dst, const void* src) {
    asm volatile("cp.async.cg.shared.global [%0], [%1], 16;" :: "r"(dst), "l"(src));
}
#define CP_COMMIT() asm volatile("cp.async.commit_group;" ::: "memory")
template<int N>
__device__ __forceinline__ void cp_wait() {
    asm volatile("cp.async.wait_group %0;" :: "n"(N) : "memory");
}
__device__ __forceinline__ void ldm_x4(uint32_t r[4], uint32_t addr) {
    asm volatile("ldmatrix.sync.aligned.m8n8.x4.shared.b16 {%0,%1,%2,%3}, [%4];"
        : "=r"(r[0]), "=r"(r[1]), "=r"(r[2]), "=r"(r[3]) : "r"(addr));
}
__device__ __forceinline__ void ldm_x4t(uint32_t r[4], uint32_t addr) {
    asm volatile("ldmatrix.sync.aligned.m8n8.x4.trans.shared.b16 {%0,%1,%2,%3}, [%4];"
        : "=r"(r[0]), "=r"(r[1]), "=r"(r[2]), "=r"(r[3]) : "r"(addr));
}
__device__ __forceinline__ void sts32(uint32_t addr, uint32_t v) {
    asm volatile("st.shared.b32 [%0], %1;" :: "r"(addr), "r"(v));
}
__device__ __forceinline__ void mma_fp16(float c[4], const uint32_t a[4],
                                         const uint32_t b0, const uint32_t b1) {
    asm volatile(
        "mma.sync.aligned.m16n8k16.row.col.f32.f16.f16.f32 "
        "{%0,%1,%2,%3}, {%4,%5,%6,%7}, {%8,%9}, {%0,%1,%2,%3};"
        : "+f"(c[0]), "+f"(c[1]), "+f"(c[2]), "+f"(c[3])
        : "r"(a[0]), "r"(a[1]), "r"(a[2]), "r"(a[3]),
          "r"(b0), "r"(b1));
}

// ---------------------------------------------------------------------------
// merged fp32 -> fp16 conversion
// ---------------------------------------------------------------------------
#define CVT_TOTAL (24*1024*1024)
#define CVT_BLOCKS (CVT_TOTAL / (256*8))

__global__ __launch_bounds__(256) void convert_all(
    const float* __restrict__ hs, const float* __restrict__ Wq,
    const float* __restrict__ Wk, const float* __restrict__ Wv,
    const float* __restrict__ Wo,
    half* __restrict__ hsh, half* __restrict__ wh, half* __restrict__ woh)
{
    const int i = (blockIdx.x * 256 + threadIdx.x) * 8;
    const float* src;
    half* dst;
    const int HS_N = Mc * Dc;
    const int W_N  = Dc * Dc;
    if (i < HS_N) {
        src = hs + i; dst = hsh + i;
    } else {
        int j = i - HS_N;
        int r = j / W_N;
        int off = j - r * W_N;
        const float* srcs[4] = {Wq, Wk, Wv, Wo};
        src = srcs[r] + off;
        dst = (r < 3) ? (wh + (size_t)r * W_N + off) : (woh + off);
    }
    float4 a = *(const float4*)src;
    float4 b = *(const float4*)(src + 4);
    uint4 u = make_uint4(pack_h2(a.x, a.y), pack_h2(a.z, a.w),
                         pack_h2(b.x, b.y), pack_h2(b.z, b.w));
    *(uint4*)dst = u;
}

// ---------------------------------------------------------------------------
// rope table
// ---------------------------------------------------------------------------
__global__ __launch_bounds__(256) void rope_table_kernel(
    const int* __restrict__ pos, float2* __restrict__ tab)
{
    int idx = blockIdx.x * 256 + threadIdx.x;
    int bs = idx >> 5, i = idx & 31;
    float inv = powf(10000.f, -(float)(2 * i) / (float)ROTc);
    float ang = (float)pos[bs] * inv;
    float sn, cs;
    sincosf(ang, &sn, &cs);
    tab[idx] = make_float2(sn, cs);
}

// ---------------------------------------------------------------------------
// fp16 GEMM core (R10/R14-proven): CTA 128x256, warp 64x64, BK=32, 3-stage
// ---------------------------------------------------------------------------
#define GBM 128
#define GBN 256
#define GBK 32
#define GA_BUF 8192u
#define GB_BUF 16384u
#define STAGES 3
#define GB_BASE ((uint32_t)STAGES * GA_BUF)
#define GEMM_SMEM (GB_BASE + (uint32_t)STAGES * GB_BUF)   // 73728

template <typename OutT>
__device__ __forceinline__ void gemm_fp16_body(
    const half* __restrict__ A, const half* __restrict__ W,
    OutT* __restrict__ C, int M, int N, int K)
{
    extern __shared__ half gsm[];
    const uint32_t S0 = smem_u32(gsm);

    const int tid  = threadIdx.x;
    const int warp = tid >> 5, lane = tid & 31;
    const int gid  = lane >> 2, tig = lane & 3;
    const int wm   = (warp >> 2) * 64, wn = (warp & 3) * 64;
    const int bm   = blockIdx.y * GBM,  bn = blockIdx.x * GBN;

    int aRow[2], aC[2]; uint32_t aDst[2];
#pragma unroll
    for (int i = 0; i < 2; i++) {
        int cid = tid + 256 * i;
        aRow[i] = cid >> 2; aC[i] = cid & 3;
        int phys = aC[i] ^ ((aRow[i] >> 1) & 3);
        aDst[i] = S0 + aRow[i] * 64 + phys * 16;
    }
    int bRow[4], bC[4]; uint32_t bDst[4];
#pragma unroll
    for (int i = 0; i < 4; i++) {
        int cid = tid + 256 * i;
        bRow[i] = cid >> 2; bC[i] = cid & 3;
        int phys = bC[i] ^ ((bRow[i] >> 1) & 3);
        bDst[i] = S0 + GB_BASE + bRow[i] * 64 + phys * 16;
    }

    uint32_t arow[4]; int axor[4];
    const int ahi = lane >> 4;
#pragma unroll
    for (int mt = 0; mt < 4; mt++) {
        int r = wm + 16 * mt + (lane & 7) + ((lane >> 3) & 1) * 8;
        arow[mt] = S0 + r * 64;
        axor[mt] = (r >> 1) & 3;
    }
    uint32_t brow[4]; int bxor[4];
    const int bhi = (lane >> 3) & 1;
#pragma unroll
    for (int n2 = 0; n2 < 4; n2++) {
        int r = wn + n2 * 16 + (lane & 7) + ((lane >> 4) & 1) * 8;
        brow[n2] = S0 + GB_BASE + r * 64;
        bxor[n2] = (r >> 1) & 3;
    }

    float acc[4][8][4];
#pragma unroll
    for (int i = 0; i < 4; i++)
#pragma unroll
        for (int j = 0; j < 8; j++)
#pragma unroll
            for (int l = 0; l < 4; l++) acc[i][j][l] = 0.f;

    const int NT = K / GBK;

#pragma unroll
    for (int s = 0; s < 2; s++) {
#pragma unroll
        for (int i = 0; i < 2; i++)
            cp16(aDst[i] + s * GA_BUF,
                 A + (size_t)(bm + aRow[i]) * K + s * GBK + aC[i] * 8);
#pragma unroll
        for (int i = 0; i < 4; i++)
            cp16(bDst[i] + s * GB_BUF,
                 W + (size_t)(bn + bRow[i]) * K + s * GBK + bC[i] * 8);
        CP_COMMIT();
    }

    for (int kt = 0; kt < NT; kt++) {
        if (kt == NT - 1) cp_wait<0>(); else cp_wait<1>();
        __syncthreads();

        if (kt + 2 < NT) {
            const int s = kt + 2;
            const uint32_t sa = (uint32_t)(s % STAGES) * GA_BUF;
            const uint32_t sb = (uint32_t)(s % STAGES) * GB_BUF;
#pragma unroll
            for (int i = 0; i < 2; i++)
                cp16(aDst[i] + sa,
                     A + (size_t)(bm + aRow[i]) * K + s * GBK + aC[i] * 8);
#pragma unroll
            for (int i = 0; i < 4; i++)
                cp16(bDst[i] + sb,
                     W + (size_t)(bn + bRow[i]) * K + s * GBK + bC[i] * 8);
            CP_COMMIT();
        }

        const uint32_t aofs = (uint32_t)(kt % STAGES) * GA_BUF;
        const uint32_t bofs = (uint32_t)(kt % STAGES) * GB_BUF;
#pragma unroll
        for (int ks = 0; ks < 2; ks++) {
            uint32_t af[4][4], bf[8][2];
#pragma unroll
            for (int mt = 0; mt < 4; mt++) {
                int chunk = 2 * ks + ahi;
                ldm_x4(af[mt], arow[mt] + aofs + (uint32_t)((chunk ^ axor[mt]) * 16));
            }
#pragma unroll
            for (int n2 = 0; n2 < 4; n2++) {
                int chunk = 2 * ks + bhi;
                uint32_t r[4];
                ldm_x4(r, brow[n2] + bofs + (uint32_t)((chunk ^ bxor[n2]) * 16));
                bf[n2*2][0] = r[0]; bf[n2*2][1] = r[1];
                bf[n2*2+1][0] = r[2]; bf[n2*2+1][1] = r[3];
            }
#pragma unroll
            for (int mt = 0; mt < 4; mt++)
#pragma unroll
                for (int nt = 0; nt < 8; nt++)
                    mma_fp16(acc[mt][nt], af[mt], bf[nt][0], bf[nt][1]);
        }
    }

#pragma unroll
    for (int mt = 0; mt < 4; mt++) {
        int r0 = bm + wm + mt * 16 + gid;
#pragma unroll
        for (int nt = 0; nt < 8; nt++) {
            int c0 = bn + wn + nt * 8 + tig * 2;
            if (sizeof(OutT) == 2) {
                half* Ch = (half*)C;
                *(uint32_t*)&Ch[(size_t)r0 * N + c0]       = pack_h2(acc[mt][nt][0], acc[mt][nt][1]);
                *(uint32_t*)&Ch[(size_t)(r0 + 8) * N + c0] = pack_h2(acc[mt][nt][2], acc[mt][nt][3]);
            } else {
                float* Cf = (float*)C;
                *(float2*)&Cf[(size_t)r0 * N + c0]       = make_float2(acc[mt][nt][0], acc[mt][nt][1]);
                *(float2*)&Cf[(size_t)(r0 + 8) * N + c0] = make_float2(acc[mt][nt][2], acc[mt][nt][3]);
            }
        }
    }
}

__global__ __launch_bounds__(256) void gemm_fp16_h(
    const half* __restrict__ A, const half* __restrict__ W,
    half* __restrict__ C, int M, int N, int K)
{ gemm_fp16_body<half>(A, W, C, M, N, K); }

__global__ __launch_bounds__(256) void gemm_fp16_f(
    const half* __restrict__ A, const half* __restrict__ W,
    float* __restrict__ C, int M, int N, int K)
{ gemm_fp16_body<float>(A, W, C, M, N, K); }

// ---------------------------------------------------------------------------
// counts
// ---------------------------------------------------------------------------
__global__ __launch_bounds__(256) void counts_kernel(
    const float* __restrict__ mask, float* __restrict__ cnt)
{
    __shared__ float part[256];
    const int b = blockIdx.x;
    const int t = threadIdx.x;
    const int base = b * Sc;

    float local[8];
    float sum = 0.f;
#pragma unroll
    for (int j = 0; j < 8; j++) {
        int s = t * 8 + j;
        float kp = (mask[base + s] == 0.f) ? 1.f : 0.f;
        sum += kp;
        local[j] = sum;
    }
    part[t] = sum;
    __syncthreads();
    if (t == 0) {
        float run = 0.f;
        for (int i = 0; i < 256; i++) { float tmp = part[i]; part[i] = run; run += tmp; }
    }
    __syncthreads();
    float off = part[t];
#pragma unroll
    for (int j = 0; j < 8; j++)
        cnt[base + t * 8 + j] = off + local[j];
}

// ---------------------------------------------------------------------------
// fused post-projection (transcendental-free hot path)
// ---------------------------------------------------------------------------
__global__ __launch_bounds__(128) void post_qkv_kernel(
    const half* __restrict__ QKV, const float2* __restrict__ rope,
    half* __restrict__ Qh, half* __restrict__ Kh, half* __restrict__ Vh,
    const float* __restrict__ mask,
    const float* __restrict__ cnt, const float* __restrict__ nc)
{
    const int bsh = blockIdx.x;
    const int h  = bsh & (Hc - 1);
    const int bs = bsh >> 4;
    const int d = threadIdx.x;
    const size_t inb = (size_t)bs * NQKV + h * HDc + d;
    const size_t outb = (size_t)bs * Dc + h * HDc + d;

    __shared__ float redq[4], redk[4];

    float xq = __half2float(QKV[inb]);
    float xk = __half2float(QKV[inb + Dc]);
    float xv = __half2float(QKV[inb + 2 * Dc]);

    float yq = xq, yk = xk;
    if (d < ROTc) {
        float2 sc = rope[bs * 32 + (d >> 1)];
        float oq = __shfl_xor_sync(0xffffffffu, xq, 1);
        float ok = __shfl_xor_sync(0xffffffffu, xk, 1);
        yq = (d & 1) ? fmaf(xq, sc.y, oq * sc.x) : fmaf(xq, sc.y, -oq * sc.x);
        yk = (d & 1) ? fmaf(xk, sc.y, ok * sc.x) : fmaf(xk, sc.y, -ok * sc.x);
    }

    float ssq = yq * yq, ssk = yk * yk;
#pragma unroll
    for (int o = 16; o; o >>= 1) {
        ssq += __shfl_xor_sync(0xffffffffu, ssq, o);
        ssk += __shfl_xor_sync(0xffffffffu, ssk, o);
    }
    if ((d & 31) == 0) { redq[d >> 5] = ssq; redk[d >> 5] = ssk; }
    __syncthreads();
    float nq = sqrtf(redq[0] + redq[1] + redq[2] + redq[3]);
    float nk = sqrtf(redk[0] + redk[1] + redk[2] + redk[3]);

    float keep = (mask[bs] == 0.f) ? 1.f : 0.f;
    Qh[outb] = __float2half(yq / fmaxf(nq, 1e-12f) * keep);
    Kh[outb] = __float2half(yk / fmaxf(nk, 1e-12f) * keep);

    float expo = 1.f / (1.f + __expf(-nc[h]));
    float c = cnt[bs];
    float p = (c > 0.f) ? exp2f(expo * log2f(c)) : 0.f;
    float scale = keep / fmaxf(p, 1.f);
    Vh[outb] = __float2half(xv * scale);
}

// ---------------------------------------------------------------------------
// fp16 tensor-core causal attention, q-tile 128, k-tile 64.
// 8 warps = 4 q-groups (32q) x 2 halves. Phase1 warp: 32q x 32k.
// Phase2 warp: 32q x 64d (V fragments shared by 4 q-warps).
// Q [128][128] 256B rows; K/V [64][128] dbl-buffered; P [128][64] 128B rows.
// Swizzle: chunk c at phys = c ^ (row&7).
// ---------------------------------------------------------------------------
#define AQ3 128
#define KT3 64
#define A3_QS  0u
#define A3_K0  32768u
#define A3_K1  49152u
#define A3_V0  65536u
#define A3_V1  81920u
#define A3_PS  98304u
#define A3_SMEM 114688

__global__ __launch_bounds__(256) void attn_fp16_128(
    const half* __restrict__ Qh, const half* __restrict__ Kh,
    const half* __restrict__ Vh, half* __restrict__ O)
{
    extern __shared__ half smh[];
    const uint32_t S0 = smem_u32(smh);

    const int bh = blockIdx.y;
    const int b = bh >> 4;
    const int h = bh & (Hc - 1);
    const int qt = gridDim.x - 1 - blockIdx.x;   // big tiles first

    const int tid  = threadIdx.x;
    const int warp = tid >> 5, lane = tid & 31;
    const int gid  = lane >> 2, tig = lane & 3;
    const int wq   = (warp >> 1) * 32;        // q group (both phases)
    const int wk   = (warp & 1) * 32;         // phase1 k half
    const int wd   = (warp & 1) * 64;         // phase2 d half

    const uint32_t kbuf[2] = {A3_K0, A3_K1};
    const uint32_t vbuf[2] = {A3_V0, A3_V1};

    // K/V staging: 4 chunks/thread
    int srow[4], sphy[4];
#pragma unroll
    for (int i = 0; i < 4; i++) {
        int cid = tid + 256 * i;
        srow[i] = cid >> 4;
        sphy[i] = (cid & 15) ^ (srow[i] & 7);
    }

    const half* Qg = Qh + ((size_t)(b * Sc + qt * AQ3)) * Dc + h * HDc;

    // prologue: Q (8 chunks/thread) + K/V tile 0
#pragma unroll
    for (int i = 0; i < 8; i++) {
        int cid = tid + 256 * i;
        int row = cid >> 4, c = cid & 15;
        cp16(S0 + A3_QS + row * 256 + ((c ^ (row & 7)) * 16),
             Qg + (size_t)row * Dc + c * 8);
    }
    {
        const half* Kg = Kh + ((size_t)(b * Sc)) * Dc + h * HDc;
        const half* Vg = Vh + ((size_t)(b * Sc)) * Dc + h * HDc;
#pragma unroll
        for (int i = 0; i < 4; i++) {
            int c = (tid + 256 * i) & 15;
            cp16(S0 + kbuf[0] + srow[i] * 256 + sphy[i] * 16,
                 Kg + (size_t)srow[i] * Dc + c * 8);
            cp16(S0 + vbuf[0] + srow[i] * 256 + sphy[i] * 16,
                 Vg + (size_t)srow[i] * Dc + c * 8);
        }
    }
    CP_COMMIT();

    float oacc[2][8][4];
#pragma unroll
    for (int m = 0; m < 2; m++)
#pragma unroll
        for (int i = 0; i < 8; i++)
#pragma unroll
            for (int l = 0; l < 4; l++) oacc[m][i][l] = 0.f;

    // ldmatrix row bases (A side; 2 m-tiles of 16)
    int arow[2], ax[2];
#pragma unroll
    for (int mt = 0; mt < 2; mt++) {
        arow[mt] = wq + mt * 16 + (lane & 7) + ((lane >> 3) & 1) * 8;
        ax[mt] = arow[mt] & 7;
    }
    const int chi = lane >> 4;
    const int ktmax = 2 * qt + 1;

    for (int kt = 0; kt <= ktmax; kt++) {
        cp_wait<0>();
        __syncthreads();

        if (kt + 1 <= ktmax) {
            const int s = kt + 1;
            const uint32_t kb = kbuf[s & 1], vb = vbuf[s & 1];
            const half* Kg = Kh + ((size_t)(b * Sc + s * KT3)) * Dc + h * HDc;
            const half* Vg = Vh + ((size_t)(b * Sc + s * KT3)) * Dc + h * HDc;
#pragma unroll
            for (int i = 0; i < 4; i++) {
                int c = (tid + 256 * i) & 15;
                cp16(S0 + kb + srow[i] * 256 + sphy[i] * 16,
                     Kg + (size_t)srow[i] * Dc + c * 8);
                cp16(S0 + vb + srow[i] * 256 + sphy[i] * 16,
                     Vg + (size_t)srow[i] * Dc + c * 8);
            }
            CP_COMMIT();
        }

        const uint32_t kbs = S0 + kbuf[kt & 1];
        const uint32_t vbs = S0 + vbuf[kt & 1];

        // ---- phase 1: P[32q x 32k] per warp over d=128 ----
        float pacc[2][4][4];
#pragma unroll
        for (int m = 0; m < 2; m++)
#pragma unroll
            for (int i = 0; i < 4; i++)
#pragma unroll
                for (int l = 0; l < 4; l++) pacc[m][i][l] = 0.f;

#pragma unroll
        for (int ks = 0; ks < 8; ks++) {
            const int c0 = ks * 2 + chi;
            uint32_t a[2][4];
#pragma unroll
            for (int mt = 0; mt < 2; mt++)
                ldm_x4(a[mt], S0 + A3_QS + arow[mt] * 256 + ((c0 ^ ax[mt]) * 16));
#pragma unroll
            for (int n2 = 0; n2 < 2; n2++) {
                int brow = wk + n2 * 16 + (lane & 7) + ((lane >> 3) & 1) * 8;
                uint32_t r[4];
                ldm_x4(r, kbs + brow * 256 + ((c0 ^ (brow & 7)) * 16));
#pragma unroll
                for (int mt = 0; mt < 2; mt++) {
                    mma_fp16(pacc[mt][2*n2],   a[mt], r[0], r[2]);
                    mma_fp16(pacc[mt][2*n2+1], a[mt], r[1], r[3]);
                }
            }
        }

        // mask (global indices, only possible on last two k-tiles) + store P
        const bool diag = (kt >= 2 * qt);
#pragma unroll
        for (int mt = 0; mt < 2; mt++) {
            int q0 = wq + mt * 16 + gid, q1 = q0 + 8;
#pragma unroll
            for (int nt = 0; nt < 4; nt++) {
                int kl0 = wk + nt * 8 + tig * 2;
                float v00 = pacc[mt][nt][0], v01 = pacc[mt][nt][1];
                float v10 = pacc[mt][nt][2], v11 = pacc[mt][nt][3];
                if (diag) {
                    int gk0 = kt * KT3 + kl0;
                    int gq0 = qt * AQ3 + q0, gq1 = gq0 + 8;
                    if (gk0     > gq0) v00 = 0.f;
                    if (gk0 + 1 > gq0) v01 = 0.f;
                    if (gk0     > gq1) v10 = 0.f;
                    if (gk0 + 1 > gq1) v11 = 0.f;
                }
                int chunk = kl0 >> 3;
                sts32(S0 + A3_PS + q0 * 128 + ((chunk ^ (q0 & 7)) * 16) + tig * 4,
                      pack_h2(v00, v01));
                sts32(S0 + A3_PS + q1 * 128 + ((chunk ^ (q1 & 7)) * 16) + tig * 4,
                      pack_h2(v10, v11));
            }
        }
        __syncthreads();

        // ---- phase 2: O[32q x 64d] per warp over k=64 ----
#pragma unroll
        for (int ks = 0; ks < 4; ks++) {
            const int ca = ks * 2 + chi;
            uint32_t a[2][4];
#pragma unroll
            for (int mt = 0; mt < 2; mt++)
                ldm_x4(a[mt], S0 + A3_PS + arow[mt] * 128 + ((ca ^ ax[mt]) * 16));
            const int vrow = ks * 16 + (lane & 7) + ((lane >> 3) & 1) * 8;
            const int vx = vrow & 7;
#pragma unroll
            for (int j = 0; j < 4; j++) {
                int cd = (wd >> 3) + j * 2 + chi;
                uint32_t r[4];
                ldm_x4t(r, vbs + vrow * 256 + ((cd ^ vx) * 16));
#pragma unroll
                for (int mt = 0; mt < 2; mt++) {
                    mma_fp16(oacc[mt][2*j],   a[mt], r[0], r[1]);
                    mma_fp16(oacc[mt][2*j+1], a[mt], r[2], r[3]);
                }
            }
        }
        // next iter's top __syncthreads subsumes end sync
    }

    // epilogue
    half* Og = O + ((size_t)(b * Sc + qt * AQ3)) * Dc + h * HDc;
#pragma unroll
    for (int mt = 0; mt < 2; mt++) {
        int q0 = wq + mt * 16 + gid, q1 = q0 + 8;
#pragma unroll
        for (int nt = 0; nt < 8; nt++) {
            int d0 = wd + nt * 8 + tig * 2;
            *(uint32_t*)&Og[(size_t)q0 * Dc + d0] = pack_h2(oacc[mt][nt][0], oacc[mt][nt][1]);
            *(uint32_t*)&Og[(size_t)q1 * Dc + d0] = pack_h2(oacc[mt][nt][2], oacc[mt][nt][3]);
        }
    }
}

// ---------------------------------------------------------------------------
// launch
// ---------------------------------------------------------------------------
extern "C" void kernel_launch(void* const* d_in, const int* in_sizes, int n_in,
                              void* d_out, int out_size)
{
    const float* hs   = (const float*)d_in[0];
    const float* mask = (const float*)d_in[1];
    const int*   pos  = (const int*)  d_in[2];
    const float* Wq   = (const float*)d_in[3];
    const float* Wk   = (const float*)d_in[4];
    const float* Wv   = (const float*)d_in[5];
    const float* Wo   = (const float*)d_in[6];
    const float* nc   = (const float*)d_in[7];
    float* out = (float*)d_out;

    float *cnt; float2 *rope;
    half *hsh, *wh, *woh, *qkvh, *abh, *qh, *kh, *vh;
    cudaGetSymbolAddress((void**)&cnt,  g_cnt);
    cudaGetSymbolAddress((void**)&rope, g_rope);
    cudaGetSymbolAddress((void**)&hsh,  g_hsh);
    cudaGetSymbolAddress((void**)&wh,   g_wh);
    cudaGetSymbolAddress((void**)&woh,  g_woh);
    cudaGetSymbolAddress((void**)&qkvh, g_qkvh);
    cudaGetSymbolAddress((void**)&abh,  g_abh);
    cudaGetSymbolAddress((void**)&qh,   g_qh);
    cudaGetSymbolAddress((void**)&kh,   g_kh);
    cudaGetSymbolAddress((void**)&vh,   g_vh);

    cudaFuncSetAttribute(gemm_fp16_h,
                         cudaFuncAttributeMaxDynamicSharedMemorySize, GEMM_SMEM);
    cudaFuncSetAttribute(gemm_fp16_f,
                         cudaFuncAttributeMaxDynamicSharedMemorySize, GEMM_SMEM);
    cudaFuncSetAttribute(attn_fp16_128,
                         cudaFuncAttributeMaxDynamicSharedMemorySize, A3_SMEM);

    counts_kernel<<<Bc, 256>>>(mask, cnt);
    rope_table_kernel<<<(Bc * Sc * 32) / 256, 256>>>(pos, rope);

    convert_all<<<CVT_BLOCKS, 256>>>(hs, Wq, Wk, Wv, Wo, hsh, wh, woh);

    dim3 qkvGrid(NQKV / GBN, Mc / GBM);   // (24, 32)
    gemm_fp16_h<<<qkvGrid, 256, GEMM_SMEM>>>(hsh, wh, qkvh, Mc, NQKV, Dc);

    const int nrows = Bc * Sc * Hc;
    post_qkv_kernel<<<nrows, 128>>>(qkvh, rope, qh, kh, vh, mask, cnt, nc);

    dim3 attnGrid(Sc / AQ3, Bc * Hc);     // (16, 32)
    attn_fp16_128<<<attnGrid, 256, A3_SMEM>>>(qh, kh, vh, abh);

    dim3 oGrid(Dc / GBN, Mc / GBM);       // (8, 32)
    gemm_fp16_f<<<oGrid, 256, GEMM_SMEM>>>(abh, woh, out, Mc, Dc, Dc);
}

// round 16
// speedup vs baseline: 1.0626x; 1.0626x over previous
#include <cuda_runtime.h>
#include <cuda_fp16.h>
#include <math.h>
#include <stdint.h>

// Problem constants
#define Bc   2
#define Sc   2048
#define Dc   2048
#define Hc   16
#define HDc  128
#define ROTc 64
#define Mc   (Bc*Sc)
#define NQKV (3*Dc)   // 6144

// ---------------------------------------------------------------------------
// Scratch
// ---------------------------------------------------------------------------
__device__ float  g_cnt[Bc*Sc];
__device__ float2 g_rope[(size_t)Bc*Sc*32];
__device__ half   g_hsh [(size_t)Mc*Dc];
__device__ half   g_wh  [(size_t)NQKV*Dc];   // packed [Wq;Wk;Wv]
__device__ half   g_woh [(size_t)Dc*Dc];
__device__ half   g_qkvh[(size_t)Mc*NQKV];
__device__ half   g_abh [(size_t)Mc*Dc];
__device__ half   g_qh  [(size_t)Mc*Dc];
__device__ half   g_kh  [(size_t)Mc*Dc];
__device__ half   g_vh  [(size_t)Mc*Dc];

// ---------------------------------------------------------------------------
// helpers
// ---------------------------------------------------------------------------
__device__ __forceinline__ uint32_t smem_u32(const void* p) {
    uint32_t a;
    asm("{ .reg .u64 t; cvta.to.shared.u64 t, %1; cvt.u32.u64 %0, t; }"
        : "=r"(a) : "l"(p));
    return a;
}
__device__ __forceinline__ uint32_t pack_h2(float lo, float hi) {
    half2 h = __floats2half2_rn(lo, hi);
    return *(uint32_t*)&h;
}
__device__ __forceinline__ void cp16(uint32_t dst, const void* src) {
    asm volatile("cp.async.cg.shared.global [%0], [%1], 16;" :: "r"(dst), "l"(src));
}
#define CP_COMMIT() asm volatile("cp.async.commit_group;" ::: "memory")
template<int N>
__device__ __forceinline__ void cp_wait() {
    asm volatile("cp.async.wait_group %0;" :: "n"(N) : "memory");
}
__device__ __forceinline__ void ldm_x4(uint32_t r[4], uint32_t addr) {
    asm volatile("ldmatrix.sync.aligned.m8n8.x4.shared.b16 {%0,%1,%2,%3}, [%4];"
        : "=r"(r[0]), "=r"(r[1]), "=r"(r[2]), "=r"(r[3]) : "r"(addr));
}
__device__ __forceinline__ void ldm_x4t(uint32_t r[4], uint32_t addr) {
    asm volatile("ldmatrix.sync.aligned.m8n8.x4.trans.shared.b16 {%0,%1,%2,%3}, [%4];"
        : "=r"(r[0]), "=r"(r[1]), "=r"(r[2]), "=r"(r[3]) : "r"(addr));
}
__device__ __forceinline__ void sts32(uint32_t addr, uint32_t v) {
    asm volatile("st.shared.b32 [%0], %1;" :: "r"(addr), "r"(v));
}
__device__ __forceinline__ void mma_fp16(float c[4], const uint32_t a[4],
                                         const uint32_t b0, const uint32_t b1) {
    asm volatile(
        "mma.sync.aligned.m16n8k16.row.col.f32.f16.f16.f32 "
        "{%0,%1,%2,%3}, {%4,%5,%6,%7}, {%8,%9}, {%0,%1,%2,%3};"
        : "+f"(c[0]), "+f"(c[1]), "+f"(c[2]), "+f"(c[3])
        : "r"(a[0]), "r"(a[1]), "r"(a[2]), "r"(a[3]),
          "r"(b0), "r"(b1));
}

// ---------------------------------------------------------------------------
// merged fp32 -> fp16 conversion
// ---------------------------------------------------------------------------
#define CVT_TOTAL (24*1024*1024)
#define CVT_BLOCKS (CVT_TOTAL / (256*8))

__global__ __launch_bounds__(256) void convert_all(
    const float* __restrict__ hs, const float* __restrict__ Wq,
    const float* __restrict__ Wk, const float* __restrict__ Wv,
    const float* __restrict__ Wo,
    half* __restrict__ hsh, half* __restrict__ wh, half* __restrict__ woh)
{
    const int i = (blockIdx.x * 256 + threadIdx.x) * 8;
    const float* src;
    half* dst;
    const int HS_N = Mc * Dc;
    const int W_N  = Dc * Dc;
    if (i < HS_N) {
        src = hs + i; dst = hsh + i;
    } else {
        int j = i - HS_N;
        int r = j / W_N;
        int off = j - r * W_N;
        const float* srcs[4] = {Wq, Wk, Wv, Wo};
        src = srcs[r] + off;
        dst = (r < 3) ? (wh + (size_t)r * W_N + off) : (woh + off);
    }
    float4 a = *(const float4*)src;
    float4 b = *(const float4*)(src + 4);
    uint4 u = make_uint4(pack_h2(a.x, a.y), pack_h2(a.z, a.w),
                         pack_h2(b.x, b.y), pack_h2(b.z, b.w));
    *(uint4*)dst = u;
}

// ---------------------------------------------------------------------------
// rope table
// ---------------------------------------------------------------------------
__global__ __launch_bounds__(256) void rope_table_kernel(
    const int* __restrict__ pos, float2* __restrict__ tab)
{
    int idx = blockIdx.x * 256 + threadIdx.x;
    int bs = idx >> 5, i = idx & 31;
    float inv = powf(10000.f, -(float)(2 * i) / (float)ROTc);
    float ang = (float)pos[bs] * inv;
    float sn, cs;
    sincosf(ang, &sn, &cs);
    tab[idx] = make_float2(sn, cs);
}

// ---------------------------------------------------------------------------
// fp16 GEMM core: CTA tile 128x256, warp tile 64x64, BK=64 (128B rows),
// cp.async 3-stage pipeline. Swizzle: 16B chunk c at phys = c ^ (row&7).
// 32 mainloop iterations (half the barrier/wait overhead of BK=32).
// ---------------------------------------------------------------------------
#define GBM 128
#define GBN 256
#define GBK 64
#define GA_BUF 16384u                                    // 128 rows * 128B
#define GB_BUF 32768u                                    // 256 rows * 128B
#define STAGES 3
#define GB_BASE ((uint32_t)STAGES * GA_BUF)              // 49152
#define GEMM_SMEM (GB_BASE + (uint32_t)STAGES * GB_BUF)  // 147456

template <typename OutT>
__device__ __forceinline__ void gemm_fp16_body(
    const half* __restrict__ A, const half* __restrict__ W,
    OutT* __restrict__ C, int M, int N, int K)
{
    extern __shared__ half gsm[];
    const uint32_t S0 = smem_u32(gsm);

    const int tid  = threadIdx.x;
    const int warp = tid >> 5, lane = tid & 31;
    const int gid  = lane >> 2, tig = lane & 3;
    const int wm   = (warp >> 2) * 64, wn = (warp & 3) * 64;
    const int bm   = blockIdx.y * GBM,  bn = blockIdx.x * GBN;

    // staging: A 4 chunks/thread (1024 chunks), B 8 chunks/thread (2048)
    int aRow[4], aC[4]; uint32_t aDst[4];
#pragma unroll
    for (int i = 0; i < 4; i++) {
        int cid = tid + 256 * i;
        aRow[i] = cid >> 3; aC[i] = cid & 7;
        int phys = aC[i] ^ (aRow[i] & 7);
        aDst[i] = S0 + aRow[i] * 128 + phys * 16;
    }
    int bRow[8], bC[8]; uint32_t bDst[8];
#pragma unroll
    for (int i = 0; i < 8; i++) {
        int cid = tid + 256 * i;
        bRow[i] = cid >> 3; bC[i] = cid & 7;
        int phys = bC[i] ^ (bRow[i] & 7);
        bDst[i] = S0 + GB_BASE + bRow[i] * 128 + phys * 16;
    }

    // ldmatrix bases
    uint32_t arow[4]; int axor[4];
    const int ahi = lane >> 4;
#pragma unroll
    for (int mt = 0; mt < 4; mt++) {
        int r = wm + 16 * mt + (lane & 7) + ((lane >> 3) & 1) * 8;
        arow[mt] = S0 + r * 128;
        axor[mt] = r & 7;
    }
    uint32_t brow[4]; int bxor[4];
    const int bhi = (lane >> 3) & 1;
#pragma unroll
    for (int n2 = 0; n2 < 4; n2++) {
        int r = wn + n2 * 16 + (lane & 7) + ((lane >> 4) & 1) * 8;
        brow[n2] = S0 + GB_BASE + r * 128;
        bxor[n2] = r & 7;
    }

    float acc[4][8][4];
#pragma unroll
    for (int i = 0; i < 4; i++)
#pragma unroll
        for (int j = 0; j < 8; j++)
#pragma unroll
            for (int l = 0; l < 4; l++) acc[i][j][l] = 0.f;

    const int NT = K / GBK;   // 32

    // prologue: stages 0,1
#pragma unroll
    for (int s = 0; s < 2; s++) {
#pragma unroll
        for (int i = 0; i < 4; i++)
            cp16(aDst[i] + s * GA_BUF,
                 A + (size_t)(bm + aRow[i]) * K + s * GBK + aC[i] * 8);
#pragma unroll
        for (int i = 0; i < 8; i++)
            cp16(bDst[i] + s * GB_BUF,
                 W + (size_t)(bn + bRow[i]) * K + s * GBK + bC[i] * 8);
        CP_COMMIT();
    }

    for (int kt = 0; kt < NT; kt++) {
        if (kt == NT - 1) cp_wait<0>(); else cp_wait<1>();
        __syncthreads();

        if (kt + 2 < NT) {
            const int s = kt + 2;
            const uint32_t sa = (uint32_t)(s % STAGES) * GA_BUF;
            const uint32_t sb = (uint32_t)(s % STAGES) * GB_BUF;
#pragma unroll
            for (int i = 0; i < 4; i++)
                cp16(aDst[i] + sa,
                     A + (size_t)(bm + aRow[i]) * K + s * GBK + aC[i] * 8);
#pragma unroll
            for (int i = 0; i < 8; i++)
                cp16(bDst[i] + sb,
                     W + (size_t)(bn + bRow[i]) * K + s * GBK + bC[i] * 8);
            CP_COMMIT();
        }

        const uint32_t aofs = (uint32_t)(kt % STAGES) * GA_BUF;
        const uint32_t bofs = (uint32_t)(kt % STAGES) * GB_BUF;
#pragma unroll
        for (int ks = 0; ks < 4; ks++) {
            uint32_t af[4][4], bf[8][2];
#pragma unroll
            for (int mt = 0; mt < 4; mt++) {
                int chunk = 2 * ks + ahi;
                ldm_x4(af[mt], arow[mt] + aofs + (uint32_t)((chunk ^ axor[mt]) * 16));
            }
#pragma unroll
            for (int n2 = 0; n2 < 4; n2++) {
                int chunk = 2 * ks + bhi;
                uint32_t r[4];
                ldm_x4(r, brow[n2] + bofs + (uint32_t)((chunk ^ bxor[n2]) * 16));
                bf[n2*2][0] = r[0]; bf[n2*2][1] = r[1];
                bf[n2*2+1][0] = r[2]; bf[n2*2+1][1] = r[3];
            }
#pragma unroll
            for (int mt = 0; mt < 4; mt++)
#pragma unroll
                for (int nt = 0; nt < 8; nt++)
                    mma_fp16(acc[mt][nt], af[mt], bf[nt][0], bf[nt][1]);
        }
    }

    // epilogue
#pragma unroll
    for (int mt = 0; mt < 4; mt++) {
        int r0 = bm + wm + mt * 16 + gid;
#pragma unroll
        for (int nt = 0; nt < 8; nt++) {
            int c0 = bn + wn + nt * 8 + tig * 2;
            if (sizeof(OutT) == 2) {
                half* Ch = (half*)C;
                *(uint32_t*)&Ch[(size_t)r0 * N + c0]       = pack_h2(acc[mt][nt][0], acc[mt][nt][1]);
                *(uint32_t*)&Ch[(size_t)(r0 + 8) * N + c0] = pack_h2(acc[mt][nt][2], acc[mt][nt][3]);
            } else {
                float* Cf = (float*)C;
                *(float2*)&Cf[(size_t)r0 * N + c0]       = make_float2(acc[mt][nt][0], acc[mt][nt][1]);
                *(float2*)&Cf[(size_t)(r0 + 8) * N + c0] = make_float2(acc[mt][nt][2], acc[mt][nt][3]);
            }
        }
    }
}

__global__ __launch_bounds__(256) void gemm_fp16_h(
    const half* __restrict__ A, const half* __restrict__ W,
    half* __restrict__ C, int M, int N, int K)
{ gemm_fp16_body<half>(A, W, C, M, N, K); }

__global__ __launch_bounds__(256) void gemm_fp16_f(
    const half* __restrict__ A, const half* __restrict__ W,
    float* __restrict__ C, int M, int N, int K)
{ gemm_fp16_body<float>(A, W, C, M, N, K); }

// ---------------------------------------------------------------------------
// counts
// ---------------------------------------------------------------------------
__global__ __launch_bounds__(256) void counts_kernel(
    const float* __restrict__ mask, float* __restrict__ cnt)
{
    __shared__ float part[256];
    const int b = blockIdx.x;
    const int t = threadIdx.x;
    const int base = b * Sc;

    float local[8];
    float sum = 0.f;
#pragma unroll
    for (int j = 0; j < 8; j++) {
        int s = t * 8 + j;
        float kp = (mask[base + s] == 0.f) ? 1.f : 0.f;
        sum += kp;
        local[j] = sum;
    }
    part[t] = sum;
    __syncthreads();
    if (t == 0) {
        float run = 0.f;
        for (int i = 0; i < 256; i++) { float tmp = part[i]; part[i] = run; run += tmp; }
    }
    __syncthreads();
    float off = part[t];
#pragma unroll
    for (int j = 0; j < 8; j++)
        cnt[base + t * 8 + j] = off + local[j];
}

// ---------------------------------------------------------------------------
// fused post-projection (transcendental-free hot path)
// ---------------------------------------------------------------------------
__global__ __launch_bounds__(128) void post_qkv_kernel(
    const half* __restrict__ QKV, const float2* __restrict__ rope,
    half* __restrict__ Qh, half* __restrict__ Kh, half* __restrict__ Vh,
    const float* __restrict__ mask,
    const float* __restrict__ cnt, const float* __restrict__ nc)
{
    const int bsh = blockIdx.x;
    const int h  = bsh & (Hc - 1);
    const int bs = bsh >> 4;
    const int d = threadIdx.x;
    const size_t inb = (size_t)bs * NQKV + h * HDc + d;
    const size_t outb = (size_t)bs * Dc + h * HDc + d;

    __shared__ float redq[4], redk[4];

    float xq = __half2float(QKV[inb]);
    float xk = __half2float(QKV[inb + Dc]);
    float xv = __half2float(QKV[inb + 2 * Dc]);

    float yq = xq, yk = xk;
    if (d < ROTc) {
        float2 sc = rope[bs * 32 + (d >> 1)];
        float oq = __shfl_xor_sync(0xffffffffu, xq, 1);
        float ok = __shfl_xor_sync(0xffffffffu, xk, 1);
        yq = (d & 1) ? fmaf(xq, sc.y, oq * sc.x) : fmaf(xq, sc.y, -oq * sc.x);
        yk = (d & 1) ? fmaf(xk, sc.y, ok * sc.x) : fmaf(xk, sc.y, -ok * sc.x);
    }

    float ssq = yq * yq, ssk = yk * yk;
#pragma unroll
    for (int o = 16; o; o >>= 1) {
        ssq += __shfl_xor_sync(0xffffffffu, ssq, o);
        ssk += __shfl_xor_sync(0xffffffffu, ssk, o);
    }
    if ((d & 31) == 0) { redq[d >> 5] = ssq; redk[d >> 5] = ssk; }
    __syncthreads();
    float nq = sqrtf(redq[0] + redq[1] + redq[2] + redq[3]);
    float nk = sqrtf(redk[0] + redk[1] + redk[2] + redk[3]);

    float keep = (mask[bs] == 0.f) ? 1.f : 0.f;
    Qh[outb] = __float2half(yq / fmaxf(nq, 1e-12f) * keep);
    Kh[outb] = __float2half(yk / fmaxf(nk, 1e-12f) * keep);

    float expo = 1.f / (1.f + __expf(-nc[h]));
    float c = cnt[bs];
    float p = (c > 0.f) ? exp2f(expo * log2f(c)) : 0.f;
    float scale = keep / fmaxf(p, 1.f);
    Vh[outb] = __float2half(xv * scale);
}

// ---------------------------------------------------------------------------
// fp16 tensor-core causal attention (R14 proven: 64q tile)
// ---------------------------------------------------------------------------
#define AQ2 64
#define ATT_QS 0u
#define ATT_KS0 16384u
#define ATT_KS1 32768u
#define ATT_VS0 49152u
#define ATT_VS1 65536u
#define ATT_PS 81920u
#define ATT_SMEM 90112

__global__ __launch_bounds__(256) void attn_fp16(
    const half* __restrict__ Qh, const half* __restrict__ Kh,
    const half* __restrict__ Vh, half* __restrict__ O)
{
    extern __shared__ half smh[];
    const uint32_t S0 = smem_u32(smh);

    const int bh = blockIdx.y;
    const int b = bh >> 4;
    const int h = bh & (Hc - 1);
    const int qt = gridDim.x - 1 - blockIdx.x;

    const int tid  = threadIdx.x;
    const int warp = tid >> 5, lane = tid & 31;
    const int gid  = lane >> 2, tig = lane & 3;
    const int wq   = (warp >> 1) * 16;
    const int wk   = (warp & 1) * 32;
    const int wd   = (warp & 1) * 64;

    const uint32_t kbuf[2] = {ATT_KS0, ATT_KS1};
    const uint32_t vbuf[2] = {ATT_VS0, ATT_VS1};

    int srow[4], sphy[4];
#pragma unroll
    for (int i = 0; i < 4; i++) {
        int cid = tid + 256 * i;
        srow[i] = cid >> 4;
        sphy[i] = (cid & 15) ^ (srow[i] & 7);
    }

    const half* Qg = Qh + ((size_t)(b * Sc + qt * AQ2)) * Dc + h * HDc;

#pragma unroll
    for (int i = 0; i < 4; i++) {
        int c = (tid + 256 * i) & 15;
        cp16(S0 + ATT_QS + srow[i] * 256 + sphy[i] * 16,
             Qg + (size_t)srow[i] * Dc + c * 8);
    }
    {
        const half* Kg = Kh + ((size_t)(b * Sc)) * Dc + h * HDc;
        const half* Vg = Vh + ((size_t)(b * Sc)) * Dc + h * HDc;
#pragma unroll
        for (int i = 0; i < 4; i++) {
            int c = (tid + 256 * i) & 15;
            cp16(S0 + kbuf[0] + srow[i] * 256 + sphy[i] * 16,
                 Kg + (size_t)srow[i] * Dc + c * 8);
            cp16(S0 + vbuf[0] + srow[i] * 256 + sphy[i] * 16,
                 Vg + (size_t)srow[i] * Dc + c * 8);
        }
    }
    CP_COMMIT();

    float oacc[8][4];
#pragma unroll
    for (int i = 0; i < 8; i++)
#pragma unroll
        for (int l = 0; l < 4; l++) oacc[i][l] = 0.f;

    const int arow1 = wq + (lane & 7) + ((lane >> 3) & 1) * 8;
    const int ax1 = arow1 & 7;
    const int chi = lane >> 4;

    for (int kt = 0; kt <= qt; kt++) {
        cp_wait<0>();
        __syncthreads();

        if (kt + 1 <= qt) {
            const int s = kt + 1;
            const uint32_t kb = kbuf[s & 1], vb = vbuf[s & 1];
            const half* Kg = Kh + ((size_t)(b * Sc + s * AQ2)) * Dc + h * HDc;
            const half* Vg = Vh + ((size_t)(b * Sc + s * AQ2)) * Dc + h * HDc;
#pragma unroll
            for (int i = 0; i < 4; i++) {
                int c = (tid + 256 * i) & 15;
                cp16(S0 + kb + srow[i] * 256 + sphy[i] * 16,
                     Kg + (size_t)srow[i] * Dc + c * 8);
                cp16(S0 + vb + srow[i] * 256 + sphy[i] * 16,
                     Vg + (size_t)srow[i] * Dc + c * 8);
            }
            CP_COMMIT();
        }

        const uint32_t kbs = S0 + kbuf[kt & 1];
        const uint32_t vbs = S0 + vbuf[kt & 1];

        float pacc[4][4];
#pragma unroll
        for (int i = 0; i < 4; i++)
#pragma unroll
            for (int l = 0; l < 4; l++) pacc[i][l] = 0.f;

#pragma unroll
        for (int ks = 0; ks < 8; ks++) {
            const int c0 = ks * 2 + chi;
            uint32_t a[4];
            ldm_x4(a, S0 + ATT_QS + arow1 * 256 + ((c0 ^ ax1) * 16));
#pragma unroll
            for (int n2 = 0; n2 < 2; n2++) {
                int brow = wk + n2 * 16 + (lane & 7) + ((lane >> 3) & 1) * 8;
                uint32_t r[4];
                ldm_x4(r, kbs + brow * 256 + ((c0 ^ (brow & 7)) * 16));
                mma_fp16(pacc[2*n2],   a, r[0], r[2]);
                mma_fp16(pacc[2*n2+1], a, r[1], r[3]);
            }
        }

        const bool diag = (kt == qt);
#pragma unroll
        for (int nt = 0; nt < 4; nt++) {
            int kl0 = wk + nt * 8 + tig * 2;
            int q0 = wq + gid, q1 = q0 + 8;
            float v00 = pacc[nt][0], v01 = pacc[nt][1];
            float v10 = pacc[nt][2], v11 = pacc[nt][3];
            if (diag) {
                if (kl0     > q0) v00 = 0.f;
                if (kl0 + 1 > q0) v01 = 0.f;
                if (kl0     > q1) v10 = 0.f;
                if (kl0 + 1 > q1) v11 = 0.f;
            }
            int chunk = kl0 >> 3;
            sts32(S0 + ATT_PS + q0 * 128 + ((chunk ^ (q0 & 7)) * 16) + tig * 4,
                  pack_h2(v00, v01));
            sts32(S0 + ATT_PS + q1 * 128 + ((chunk ^ (q1 & 7)) * 16) + tig * 4,
                  pack_h2(v10, v11));
        }
        __syncthreads();

#pragma unroll
        for (int ks = 0; ks < 4; ks++) {
            const int ca = ks * 2 + chi;
            uint32_t a[4];
            ldm_x4(a, S0 + ATT_PS + arow1 * 128 + ((ca ^ ax1) * 16));
            const int vrow = ks * 16 + (lane & 7) + ((lane >> 3) & 1) * 8;
            const int vx = vrow & 7;
#pragma unroll
            for (int j = 0; j < 4; j++) {
                int cd = (wd >> 3) + j * 2 + chi;
                uint32_t r[4];
                ldm_x4t(r, vbs + vrow * 256 + ((cd ^ vx) * 16));
                mma_fp16(oacc[2*j],   a, r[0], r[1]);
                mma_fp16(oacc[2*j+1], a, r[2], r[3]);
            }
        }
        // next iter's top __syncthreads subsumes end sync
    }

    half* Og = O + ((size_t)(b * Sc + qt * AQ2)) * Dc + h * HDc;
    int q0 = wq + gid, q1 = q0 + 8;
#pragma unroll
    for (int nt = 0; nt < 8; nt++) {
        int d0 = wd + nt * 8 + tig * 2;
        *(uint32_t*)&Og[(size_t)q0 * Dc + d0] = pack_h2(oacc[nt][0], oacc[nt][1]);
        *(uint32_t*)&Og[(size_t)q1 * Dc + d0] = pack_h2(oacc[nt][2], oacc[nt][3]);
    }
}

// ---------------------------------------------------------------------------
// launch
// ---------------------------------------------------------------------------
extern "C" void kernel_launch(void* const* d_in, const int* in_sizes, int n_in,
                              void* d_out, int out_size)
{
    const float* hs   = (const float*)d_in[0];
    const float* mask = (const float*)d_in[1];
    const int*   pos  = (const int*)  d_in[2];
    const float* Wq   = (const float*)d_in[3];
    const float* Wk   = (const float*)d_in[4];
    const float* Wv   = (const float*)d_in[5];
    const float* Wo   = (const float*)d_in[6];
    const float* nc   = (const float*)d_in[7];
    float* out = (float*)d_out;

    float *cnt; float2 *rope;
    half *hsh, *wh, *woh, *qkvh, *abh, *qh, *kh, *vh;
    cudaGetSymbolAddress((void**)&cnt,  g_cnt);
    cudaGetSymbolAddress((void**)&rope, g_rope);
    cudaGetSymbolAddress((void**)&hsh,  g_hsh);
    cudaGetSymbolAddress((void**)&wh,   g_wh);
    cudaGetSymbolAddress((void**)&woh,  g_woh);
    cudaGetSymbolAddress((void**)&qkvh, g_qkvh);
    cudaGetSymbolAddress((void**)&abh,  g_abh);
    cudaGetSymbolAddress((void**)&qh,   g_qh);
    cudaGetSymbolAddress((void**)&kh,   g_kh);
    cudaGetSymbolAddress((void**)&vh,   g_vh);

    cudaFuncSetAttribute(gemm_fp16_h,
                         cudaFuncAttributeMaxDynamicSharedMemorySize, GEMM_SMEM);
    cudaFuncSetAttribute(gemm_fp16_f,
                         cudaFuncAttributeMaxDynamicSharedMemorySize, GEMM_SMEM);
    cudaFuncSetAttribute(attn_fp16,
                         cudaFuncAttributeMaxDynamicSharedMemorySize, ATT_SMEM);

    counts_kernel<<<Bc, 256>>>(mask, cnt);
    rope_table_kernel<<<(Bc * Sc * 32) / 256, 256>>>(pos, rope);

    convert_all<<<CVT_BLOCKS, 256>>>(hs, Wq, Wk, Wv, Wo, hsh, wh, woh);

    dim3 qkvGrid(NQKV / GBN, Mc / GBM);   // (24, 32)
    gemm_fp16_h<<<qkvGrid, 256, GEMM_SMEM>>>(hsh, wh, qkvh, Mc, NQKV, Dc);

    const int nrows = Bc * Sc * Hc;
    post_qkv_kernel<<<nrows, 128>>>(qkvh, rope, qh, kh, vh, mask, cnt, nc);

    dim3 attnGrid(Sc / AQ2, Bc * Hc);     // (32, 32)
    attn_fp16<<<attnGrid, 256, ATT_SMEM>>>(qh, kh, vh, abh);

    dim3 oGrid(Dc / GBN, Mc / GBM);       // (8, 32)
    gemm_fp16_f<<<oGrid, 256, GEMM_SMEM>>>(abh, woh, out, Mc, Dc, Dc);
}

// round 17
// speedup vs baseline: 1.0702x; 1.0072x over previous
#include <cuda_runtime.h>
#include <cuda_fp16.h>
#include <math.h>
#include <stdint.h>

// Problem constants
#define Bc   2
#define Sc   2048
#define Dc   2048
#define Hc   16
#define HDc  128
#define ROTc 64
#define Mc   (Bc*Sc)
#define NQKV (3*Dc)   // 6144

// ---------------------------------------------------------------------------
// Scratch
// ---------------------------------------------------------------------------
__device__ float  g_cnt[Bc*Sc];
__device__ float2 g_rope[(size_t)Bc*Sc*32];
__device__ half   g_hsh [(size_t)Mc*Dc];
__device__ half   g_wh  [(size_t)NQKV*Dc];   // packed [Wq;Wk;Wv]
__device__ half   g_woh [(size_t)Dc*Dc];
__device__ half   g_qkvh[(size_t)Mc*NQKV];
__device__ half   g_abh [(size_t)Mc*Dc];
__device__ half   g_qh  [(size_t)Mc*Dc];
__device__ half   g_kh  [(size_t)Mc*Dc];
__device__ half   g_vh  [(size_t)Mc*Dc];

// ---------------------------------------------------------------------------
// helpers
// ---------------------------------------------------------------------------
__device__ __forceinline__ uint32_t smem_u32(const void* p) {
    uint32_t a;
    asm("{ .reg .u64 t; cvta.to.shared.u64 t, %1; cvt.u32.u64 %0, t; }"
        : "=r"(a) : "l"(p));
    return a;
}
__device__ __forceinline__ uint32_t pack_h2(float lo, float hi) {
    half2 h = __floats2half2_rn(lo, hi);
    return *(uint32_t*)&h;
}
__device__ __forceinline__ void cp16(uint32_t dst, const void* src) {
    asm volatile("cp.async.cg.shared.global [%0], [%1], 16;" :: "r"(dst), "l"(src));
}
#define CP_COMMIT() asm volatile("cp.async.commit_group;" ::: "memory")
template<int N>
__device__ __forceinline__ void cp_wait() {
    asm volatile("cp.async.wait_group %0;" :: "n"(N) : "memory");
}
__device__ __forceinline__ void ldm_x4(uint32_t r[4], uint32_t addr) {
    asm volatile("ldmatrix.sync.aligned.m8n8.x4.shared.b16 {%0,%1,%2,%3}, [%4];"
        : "=r"(r[0]), "=r"(r[1]), "=r"(r[2]), "=r"(r[3]) : "r"(addr));
}
__device__ __forceinline__ void ldm_x4t(uint32_t r[4], uint32_t addr) {
    asm volatile("ldmatrix.sync.aligned.m8n8.x4.trans.shared.b16 {%0,%1,%2,%3}, [%4];"
        : "=r"(r[0]), "=r"(r[1]), "=r"(r[2]), "=r"(r[3]) : "r"(addr));
}
__device__ __forceinline__ void mma_fp16(float c[4], const uint32_t a[4],
                                         const uint32_t b0, const uint32_t b1) {
    asm volatile(
        "mma.sync.aligned.m16n8k16.row.col.f32.f16.f16.f32 "
        "{%0,%1,%2,%3}, {%4,%5,%6,%7}, {%8,%9}, {%0,%1,%2,%3};"
        : "+f"(c[0]), "+f"(c[1]), "+f"(c[2]), "+f"(c[3])
        : "r"(a[0]), "r"(a[1]), "r"(a[2]), "r"(a[3]),
          "r"(b0), "r"(b1));
}

// ---------------------------------------------------------------------------
// merged fp32 -> fp16 conversion
// ---------------------------------------------------------------------------
#define CVT_TOTAL (24*1024*1024)
#define CVT_BLOCKS (CVT_TOTAL / (256*8))

__global__ __launch_bounds__(256) void convert_all(
    const float* __restrict__ hs, const float* __restrict__ Wq,
    const float* __restrict__ Wk, const float* __restrict__ Wv,
    const float* __restrict__ Wo,
    half* __restrict__ hsh, half* __restrict__ wh, half* __restrict__ woh)
{
    const int i = (blockIdx.x * 256 + threadIdx.x) * 8;
    const float* src;
    half* dst;
    const int HS_N = Mc * Dc;
    const int W_N  = Dc * Dc;
    if (i < HS_N) {
        src = hs + i; dst = hsh + i;
    } else {
        int j = i - HS_N;
        int r = j / W_N;
        int off = j - r * W_N;
        const float* srcs[4] = {Wq, Wk, Wv, Wo};
        src = srcs[r] + off;
        dst = (r < 3) ? (wh + (size_t)r * W_N + off) : (woh + off);
    }
    float4 a = *(const float4*)src;
    float4 b = *(const float4*)(src + 4);
    uint4 u = make_uint4(pack_h2(a.x, a.y), pack_h2(a.z, a.w),
                         pack_h2(b.x, b.y), pack_h2(b.z, b.w));
    *(uint4*)dst = u;
}

// ---------------------------------------------------------------------------
// rope table
// ---------------------------------------------------------------------------
__global__ __launch_bounds__(256) void rope_table_kernel(
    const int* __restrict__ pos, float2* __restrict__ tab)
{
    int idx = blockIdx.x * 256 + threadIdx.x;
    int bs = idx >> 5, i = idx & 31;
    float inv = powf(10000.f, -(float)(2 * i) / (float)ROTc);
    float ang = (float)pos[bs] * inv;
    float sn, cs;
    sincosf(ang, &sn, &cs);
    tab[idx] = make_float2(sn, cs);
}

// ---------------------------------------------------------------------------
// fp16 GEMM core (R16-proven): CTA 128x256, warp 64x64, BK=64, 3-stage.
// Swizzle: 16B chunk c at phys = c ^ (row&7) on 128B rows.
// ---------------------------------------------------------------------------
#define GBM 128
#define GBN 256
#define GBK 64
#define GA_BUF 16384u
#define GB_BUF 32768u
#define STAGES 3
#define GB_BASE ((uint32_t)STAGES * GA_BUF)
#define GEMM_SMEM (GB_BASE + (uint32_t)STAGES * GB_BUF)   // 147456

template <typename OutT>
__device__ __forceinline__ void gemm_fp16_body(
    const half* __restrict__ A, const half* __restrict__ W,
    OutT* __restrict__ C, int M, int N, int K)
{
    extern __shared__ half gsm[];
    const uint32_t S0 = smem_u32(gsm);

    const int tid  = threadIdx.x;
    const int warp = tid >> 5, lane = tid & 31;
    const int gid  = lane >> 2, tig = lane & 3;
    const int wm   = (warp >> 2) * 64, wn = (warp & 3) * 64;
    const int bm   = blockIdx.y * GBM,  bn = blockIdx.x * GBN;

    int aRow[4], aC[4]; uint32_t aDst[4];
#pragma unroll
    for (int i = 0; i < 4; i++) {
        int cid = tid + 256 * i;
        aRow[i] = cid >> 3; aC[i] = cid & 7;
        int phys = aC[i] ^ (aRow[i] & 7);
        aDst[i] = S0 + aRow[i] * 128 + phys * 16;
    }
    int bRow[8], bC[8]; uint32_t bDst[8];
#pragma unroll
    for (int i = 0; i < 8; i++) {
        int cid = tid + 256 * i;
        bRow[i] = cid >> 3; bC[i] = cid & 7;
        int phys = bC[i] ^ (bRow[i] & 7);
        bDst[i] = S0 + GB_BASE + bRow[i] * 128 + phys * 16;
    }

    uint32_t arow[4]; int axor[4];
    const int ahi = lane >> 4;
#pragma unroll
    for (int mt = 0; mt < 4; mt++) {
        int r = wm + 16 * mt + (lane & 7) + ((lane >> 3) & 1) * 8;
        arow[mt] = S0 + r * 128;
        axor[mt] = r & 7;
    }
    uint32_t brow[4]; int bxor[4];
    const int bhi = (lane >> 3) & 1;
#pragma unroll
    for (int n2 = 0; n2 < 4; n2++) {
        int r = wn + n2 * 16 + (lane & 7) + ((lane >> 4) & 1) * 8;
        brow[n2] = S0 + GB_BASE + r * 128;
        bxor[n2] = r & 7;
    }

    float acc[4][8][4];
#pragma unroll
    for (int i = 0; i < 4; i++)
#pragma unroll
        for (int j = 0; j < 8; j++)
#pragma unroll
            for (int l = 0; l < 4; l++) acc[i][j][l] = 0.f;

    const int NT = K / GBK;   // 32

#pragma unroll
    for (int s = 0; s < 2; s++) {
#pragma unroll
        for (int i = 0; i < 4; i++)
            cp16(aDst[i] + s * GA_BUF,
                 A + (size_t)(bm + aRow[i]) * K + s * GBK + aC[i] * 8);
#pragma unroll
        for (int i = 0; i < 8; i++)
            cp16(bDst[i] + s * GB_BUF,
                 W + (size_t)(bn + bRow[i]) * K + s * GBK + bC[i] * 8);
        CP_COMMIT();
    }

    for (int kt = 0; kt < NT; kt++) {
        if (kt == NT - 1) cp_wait<0>(); else cp_wait<1>();
        __syncthreads();

        if (kt + 2 < NT) {
            const int s = kt + 2;
            const uint32_t sa = (uint32_t)(s % STAGES) * GA_BUF;
            const uint32_t sb = (uint32_t)(s % STAGES) * GB_BUF;
#pragma unroll
            for (int i = 0; i < 4; i++)
                cp16(aDst[i] + sa,
                     A + (size_t)(bm + aRow[i]) * K + s * GBK + aC[i] * 8);
#pragma unroll
            for (int i = 0; i < 8; i++)
                cp16(bDst[i] + sb,
                     W + (size_t)(bn + bRow[i]) * K + s * GBK + bC[i] * 8);
            CP_COMMIT();
        }

        const uint32_t aofs = (uint32_t)(kt % STAGES) * GA_BUF;
        const uint32_t bofs = (uint32_t)(kt % STAGES) * GB_BUF;
#pragma unroll
        for (int ks = 0; ks < 4; ks++) {
            uint32_t af[4][4], bf[8][2];
#pragma unroll
            for (int mt = 0; mt < 4; mt++) {
                int chunk = 2 * ks + ahi;
                ldm_x4(af[mt], arow[mt] + aofs + (uint32_t)((chunk ^ axor[mt]) * 16));
            }
#pragma unroll
            for (int n2 = 0; n2 < 4; n2++) {
                int chunk = 2 * ks + bhi;
                uint32_t r[4];
                ldm_x4(r, brow[n2] + bofs + (uint32_t)((chunk ^ bxor[n2]) * 16));
                bf[n2*2][0] = r[0]; bf[n2*2][1] = r[1];
                bf[n2*2+1][0] = r[2]; bf[n2*2+1][1] = r[3];
            }
#pragma unroll
            for (int mt = 0; mt < 4; mt++)
#pragma unroll
                for (int nt = 0; nt < 8; nt++)
                    mma_fp16(acc[mt][nt], af[mt], bf[nt][0], bf[nt][1]);
        }
    }

#pragma unroll
    for (int mt = 0; mt < 4; mt++) {
        int r0 = bm + wm + mt * 16 + gid;
#pragma unroll
        for (int nt = 0; nt < 8; nt++) {
            int c0 = bn + wn + nt * 8 + tig * 2;
            if (sizeof(OutT) == 2) {
                half* Ch = (half*)C;
                *(uint32_t*)&Ch[(size_t)r0 * N + c0]       = pack_h2(acc[mt][nt][0], acc[mt][nt][1]);
                *(uint32_t*)&Ch[(size_t)(r0 + 8) * N + c0] = pack_h2(acc[mt][nt][2], acc[mt][nt][3]);
            } else {
                float* Cf = (float*)C;
                *(float2*)&Cf[(size_t)r0 * N + c0]       = make_float2(acc[mt][nt][0], acc[mt][nt][1]);
                *(float2*)&Cf[(size_t)(r0 + 8) * N + c0] = make_float2(acc[mt][nt][2], acc[mt][nt][3]);
            }
        }
    }
}

__global__ __launch_bounds__(256) void gemm_fp16_h(
    const half* __restrict__ A, const half* __restrict__ W,
    half* __restrict__ C, int M, int N, int K)
{ gemm_fp16_body<half>(A, W, C, M, N, K); }

__global__ __launch_bounds__(256) void gemm_fp16_f(
    const half* __restrict__ A, const half* __restrict__ W,
    float* __restrict__ C, int M, int N, int K)
{ gemm_fp16_body<float>(A, W, C, M, N, K); }

// ---------------------------------------------------------------------------
// counts
// ---------------------------------------------------------------------------
__global__ __launch_bounds__(256) void counts_kernel(
    const float* __restrict__ mask, float* __restrict__ cnt)
{
    __shared__ float part[256];
    const int b = blockIdx.x;
    const int t = threadIdx.x;
    const int base = b * Sc;

    float local[8];
    float sum = 0.f;
#pragma unroll
    for (int j = 0; j < 8; j++) {
        int s = t * 8 + j;
        float kp = (mask[base + s] == 0.f) ? 1.f : 0.f;
        sum += kp;
        local[j] = sum;
    }
    part[t] = sum;
    __syncthreads();
    if (t == 0) {
        float run = 0.f;
        for (int i = 0; i < 256; i++) { float tmp = part[i]; part[i] = run; run += tmp; }
    }
    __syncthreads();
    float off = part[t];
#pragma unroll
    for (int j = 0; j < 8; j++)
        cnt[base + t * 8 + j] = off + local[j];
}

// ---------------------------------------------------------------------------
// fused post-projection (transcendental-free hot path)
// ---------------------------------------------------------------------------
__global__ __launch_bounds__(128) void post_qkv_kernel(
    const half* __restrict__ QKV, const float2* __restrict__ rope,
    half* __restrict__ Qh, half* __restrict__ Kh, half* __restrict__ Vh,
    const float* __restrict__ mask,
    const float* __restrict__ cnt, const float* __restrict__ nc)
{
    const int bsh = blockIdx.x;
    const int h  = bsh & (Hc - 1);
    const int bs = bsh >> 4;
    const int d = threadIdx.x;
    const size_t inb = (size_t)bs * NQKV + h * HDc + d;
    const size_t outb = (size_t)bs * Dc + h * HDc + d;

    __shared__ float redq[4], redk[4];

    float xq = __half2float(QKV[inb]);
    float xk = __half2float(QKV[inb + Dc]);
    float xv = __half2float(QKV[inb + 2 * Dc]);

    float yq = xq, yk = xk;
    if (d < ROTc) {
        float2 sc = rope[bs * 32 + (d >> 1)];
        float oq = __shfl_xor_sync(0xffffffffu, xq, 1);
        float ok = __shfl_xor_sync(0xffffffffu, xk, 1);
        yq = (d & 1) ? fmaf(xq, sc.y, oq * sc.x) : fmaf(xq, sc.y, -oq * sc.x);
        yk = (d & 1) ? fmaf(xk, sc.y, ok * sc.x) : fmaf(xk, sc.y, -ok * sc.x);
    }

    float ssq = yq * yq, ssk = yk * yk;
#pragma unroll
    for (int o = 16; o; o >>= 1) {
        ssq += __shfl_xor_sync(0xffffffffu, ssq, o);
        ssk += __shfl_xor_sync(0xffffffffu, ssk, o);
    }
    if ((d & 31) == 0) { redq[d >> 5] = ssq; redk[d >> 5] = ssk; }
    __syncthreads();
    float nq = sqrtf(redq[0] + redq[1] + redq[2] + redq[3]);
    float nk = sqrtf(redk[0] + redk[1] + redk[2] + redk[3]);

    float keep = (mask[bs] == 0.f) ? 1.f : 0.f;
    Qh[outb] = __float2half(yq / fmaxf(nq, 1e-12f) * keep);
    Kh[outb] = __float2half(yk / fmaxf(nk, 1e-12f) * keep);

    float expo = 1.f / (1.f + __expf(-nc[h]));
    float c = cnt[bs];
    float p = (c > 0.f) ? exp2f(expo * log2f(c)) : 0.f;
    float scale = keep / fmaxf(p, 1.f);
    Vh[outb] = __float2half(xv * scale);
}

// ---------------------------------------------------------------------------
// fp16 tensor-core causal attention, 64q tile, P kept in registers
// (C-fragment == A-fragment trick). Each warp: P[16q x 32k] -> O partial
// [16q x 128d] over its own 32 V rows; pairwise O reduce at the end.
// One barrier per k-iteration.
// ---------------------------------------------------------------------------
#define AQ2 64
#define ATT_QS 0u
#define ATT_KS0 16384u
#define ATT_KS1 32768u
#define ATT_VS0 49152u
#define ATT_VS1 65536u
#define ATT_SMEM 81920

__global__ __launch_bounds__(256) void attn_fp16(
    const half* __restrict__ Qh, const half* __restrict__ Kh,
    const half* __restrict__ Vh, half* __restrict__ O)
{
    extern __shared__ half smh[];
    const uint32_t S0 = smem_u32(smh);

    const int bh = blockIdx.y;
    const int b = bh >> 4;
    const int h = bh & (Hc - 1);
    const int qt = gridDim.x - 1 - blockIdx.x;

    const int tid  = threadIdx.x;
    const int warp = tid >> 5, lane = tid & 31;
    const int gid  = lane >> 2, tig = lane & 3;
    const int wq   = (warp >> 1) * 16;
    const int wk   = (warp & 1) * 32;        // this warp's k half

    const uint32_t kbuf[2] = {ATT_KS0, ATT_KS1};
    const uint32_t vbuf[2] = {ATT_VS0, ATT_VS1};

    int srow[4], sphy[4];
#pragma unroll
    for (int i = 0; i < 4; i++) {
        int cid = tid + 256 * i;
        srow[i] = cid >> 4;
        sphy[i] = (cid & 15) ^ (srow[i] & 7);
    }

    const half* Qg = Qh + ((size_t)(b * Sc + qt * AQ2)) * Dc + h * HDc;

#pragma unroll
    for (int i = 0; i < 4; i++) {
        int c = (tid + 256 * i) & 15;
        cp16(S0 + ATT_QS + srow[i] * 256 + sphy[i] * 16,
             Qg + (size_t)srow[i] * Dc + c * 8);
    }
    {
        const half* Kg = Kh + ((size_t)(b * Sc)) * Dc + h * HDc;
        const half* Vg = Vh + ((size_t)(b * Sc)) * Dc + h * HDc;
#pragma unroll
        for (int i = 0; i < 4; i++) {
            int c = (tid + 256 * i) & 15;
            cp16(S0 + kbuf[0] + srow[i] * 256 + sphy[i] * 16,
                 Kg + (size_t)srow[i] * Dc + c * 8);
            cp16(S0 + vbuf[0] + srow[i] * 256 + sphy[i] * 16,
                 Vg + (size_t)srow[i] * Dc + c * 8);
        }
    }
    CP_COMMIT();

    // O partial: 16q x 128d = 16 n-tiles of 8
    float oacc[16][4];
#pragma unroll
    for (int i = 0; i < 16; i++)
#pragma unroll
        for (int l = 0; l < 4; l++) oacc[i][l] = 0.f;

    const int arow1 = wq + (lane & 7) + ((lane >> 3) & 1) * 8;
    const int ax1 = arow1 & 7;
    const int chi = lane >> 4;

    for (int kt = 0; kt <= qt; kt++) {
        cp_wait<0>();
        __syncthreads();   // buffer rotation + data-ready

        if (kt + 1 <= qt) {
            const int s = kt + 1;
            const uint32_t kb = kbuf[s & 1], vb = vbuf[s & 1];
            const half* Kg = Kh + ((size_t)(b * Sc + s * AQ2)) * Dc + h * HDc;
            const half* Vg = Vh + ((size_t)(b * Sc + s * AQ2)) * Dc + h * HDc;
#pragma unroll
            for (int i = 0; i < 4; i++) {
                int c = (tid + 256 * i) & 15;
                cp16(S0 + kb + srow[i] * 256 + sphy[i] * 16,
                     Kg + (size_t)srow[i] * Dc + c * 8);
                cp16(S0 + vb + srow[i] * 256 + sphy[i] * 16,
                     Vg + (size_t)srow[i] * Dc + c * 8);
            }
            CP_COMMIT();
        }

        const uint32_t kbs = S0 + kbuf[kt & 1];
        const uint32_t vbs = S0 + vbuf[kt & 1];

        // ---- phase 1: P[16q x 32k] over d=128 ----
        float pacc[4][4];
#pragma unroll
        for (int i = 0; i < 4; i++)
#pragma unroll
            for (int l = 0; l < 4; l++) pacc[i][l] = 0.f;

#pragma unroll
        for (int ks = 0; ks < 8; ks++) {
            const int c0 = ks * 2 + chi;
            uint32_t a[4];
            ldm_x4(a, S0 + ATT_QS + arow1 * 256 + ((c0 ^ ax1) * 16));
#pragma unroll
            for (int n2 = 0; n2 < 2; n2++) {
                int brow = wk + n2 * 16 + (lane & 7) + ((lane >> 3) & 1) * 8;
                uint32_t r[4];
                ldm_x4(r, kbs + brow * 256 + ((c0 ^ (brow & 7)) * 16));
                mma_fp16(pacc[2*n2],   a, r[0], r[2]);
                mma_fp16(pacc[2*n2+1], a, r[1], r[3]);
            }
        }

        // mask in registers (diag tile only)
        if (kt == qt) {
#pragma unroll
            for (int nt = 0; nt < 4; nt++) {
                int kl0 = wk + nt * 8 + tig * 2;
                int q0 = wq + gid, q1 = q0 + 8;
                if (kl0     > q0) pacc[nt][0] = 0.f;
                if (kl0 + 1 > q0) pacc[nt][1] = 0.f;
                if (kl0     > q1) pacc[nt][2] = 0.f;
                if (kl0 + 1 > q1) pacc[nt][3] = 0.f;
            }
        }

        // convert P accumulator fragments -> A operand fragments (in regs)
        uint32_t ap[2][4];
#pragma unroll
        for (int kk2 = 0; kk2 < 2; kk2++) {
            ap[kk2][0] = pack_h2(pacc[2*kk2][0],   pacc[2*kk2][1]);
            ap[kk2][1] = pack_h2(pacc[2*kk2][2],   pacc[2*kk2][3]);
            ap[kk2][2] = pack_h2(pacc[2*kk2+1][0], pacc[2*kk2+1][1]);
            ap[kk2][3] = pack_h2(pacc[2*kk2+1][2], pacc[2*kk2+1][3]);
        }

        // ---- phase 2: O += P_reg . V[own 32 k rows, 128 d] ----
#pragma unroll
        for (int kk2 = 0; kk2 < 2; kk2++) {
            const int vrow = wk + kk2 * 16 + (lane & 7) + ((lane >> 3) & 1) * 8;
            const int vx = vrow & 7;
#pragma unroll
            for (int j = 0; j < 8; j++) {
                int cd = j * 2 + chi;
                uint32_t r[4];
                ldm_x4t(r, vbs + vrow * 256 + ((cd ^ vx) * 16));
                mma_fp16(oacc[2*j],   ap[kk2], r[0], r[1]);
                mma_fp16(oacc[2*j+1], ap[kk2], r[2], r[3]);
            }
        }
        // no mid barrier; next iter's top barrier protects buffers
    }

    // ---- pairwise O reduction across the two k-half warps ----
    __syncthreads();   // all compute done; safe to reuse Q/K0 smem regions
    const uint32_t rbase = S0 + (uint32_t)(warp >> 1) * 8192u;  // 4 pairs x 8KB
    if (warp & 1) {
#pragma unroll
        for (int nt = 0; nt < 16; nt++) {
            uint32_t o0 = rbase + (uint32_t)((gid * 128 + nt * 8 + tig * 2) * 4);
            uint32_t o1 = rbase + (uint32_t)(((gid + 8) * 128 + nt * 8 + tig * 2) * 4);
            asm volatile("st.shared.v2.f32 [%0], {%1,%2};" ::
                "r"(o0), "f"(oacc[nt][0]), "f"(oacc[nt][1]));
            asm volatile("st.shared.v2.f32 [%0], {%1,%2};" ::
                "r"(o1), "f"(oacc[nt][2]), "f"(oacc[nt][3]));
        }
    }
    __syncthreads();

    if (!(warp & 1)) {
        half* Og = O + ((size_t)(b * Sc + qt * AQ2)) * Dc + h * HDc;
        int q0 = wq + gid, q1 = q0 + 8;
#pragma unroll
        for (int nt = 0; nt < 16; nt++) {
            uint32_t o0 = rbase + (uint32_t)((gid * 128 + nt * 8 + tig * 2) * 4);
            uint32_t o1 = rbase + (uint32_t)(((gid + 8) * 128 + nt * 8 + tig * 2) * 4);
            float p0, p1, p2, p3;
            asm volatile("ld.shared.v2.f32 {%0,%1}, [%2];"
                : "=f"(p0), "=f"(p1) : "r"(o0));
            asm volatile("ld.shared.v2.f32 {%0,%1}, [%2];"
                : "=f"(p2), "=f"(p3) : "r"(o1));
            int d0 = nt * 8 + tig * 2;
            *(uint32_t*)&Og[(size_t)q0 * Dc + d0] =
                pack_h2(oacc[nt][0] + p0, oacc[nt][1] + p1);
            *(uint32_t*)&Og[(size_t)q1 * Dc + d0] =
                pack_h2(oacc[nt][2] + p2, oacc[nt][3] + p3);
        }
    }
}

// ---------------------------------------------------------------------------
// launch
// ---------------------------------------------------------------------------
extern "C" void kernel_launch(void* const* d_in, const int* in_sizes, int n_in,
                              void* d_out, int out_size)
{
    const float* hs   = (const float*)d_in[0];
    const float* mask = (const float*)d_in[1];
    const int*   pos  = (const int*)  d_in[2];
    const float* Wq   = (const float*)d_in[3];
    const float* Wk   = (const float*)d_in[4];
    const float* Wv   = (const float*)d_in[5];
    const float* Wo   = (const float*)d_in[6];
    const float* nc   = (const float*)d_in[7];
    float* out = (float*)d_out;

    float *cnt; float2 *rope;
    half *hsh, *wh, *woh, *qkvh, *abh, *qh, *kh, *vh;
    cudaGetSymbolAddress((void**)&cnt,  g_cnt);
    cudaGetSymbolAddress((void**)&rope, g_rope);
    cudaGetSymbolAddress((void**)&hsh,  g_hsh);
    cudaGetSymbolAddress((void**)&wh,   g_wh);
    cudaGetSymbolAddress((void**)&woh,  g_woh);
    cudaGetSymbolAddress((void**)&qkvh, g_qkvh);
    cudaGetSymbolAddress((void**)&abh,  g_abh);
    cudaGetSymbolAddress((void**)&qh,   g_qh);
    cudaGetSymbolAddress((void**)&kh,   g_kh);
    cudaGetSymbolAddress((void**)&vh,   g_vh);

    cudaFuncSetAttribute(gemm_fp16_h,
                         cudaFuncAttributeMaxDynamicSharedMemorySize, GEMM_SMEM);
    cudaFuncSetAttribute(gemm_fp16_f,
                         cudaFuncAttributeMaxDynamicSharedMemorySize, GEMM_SMEM);
    cudaFuncSetAttribute(attn_fp16,
                         cudaFuncAttributeMaxDynamicSharedMemorySize, ATT_SMEM);

    counts_kernel<<<Bc, 256>>>(mask, cnt);
    rope_table_kernel<<<(Bc * Sc * 32) / 256, 256>>>(pos, rope);

    convert_all<<<CVT_BLOCKS, 256>>>(hs, Wq, Wk, Wv, Wo, hsh, wh, woh);

    dim3 qkvGrid(NQKV / GBN, Mc / GBM);   // (24, 32)
    gemm_fp16_h<<<qkvGrid, 256, GEMM_SMEM>>>(hsh, wh, qkvh, Mc, NQKV, Dc);

    const int nrows = Bc * Sc * Hc;
    post_qkv_kernel<<<nrows, 128>>>(qkvh, rope, qh, kh, vh, mask, cnt, nc);

    dim3 attnGrid(Sc / AQ2, Bc * Hc);     // (32, 32)
    attn_fp16<<<attnGrid, 256, ATT_SMEM>>>(qh, kh, vh, abh);

    dim3 oGrid(Dc / GBN, Mc / GBM);       // (8, 32)
    gemm_fp16_f<<<oGrid, 256, GEMM_SMEM>>>(abh, woh, out, Mc, Dc, Dc);
}